// round 10
// baseline (speedup 1.0000x reference)
#include <cuda_runtime.h>
#include <cfloat>
#include <cstdint>

// Problem: V [1024, 8192] fp32 -> out [1024, 8192] fp32
#define Mm    8192
#define Nn    1024
#define STEPS 8192          // 8 rounds * 1024 rows
#define C     8             // cluster CTAs
#define TPB   256           // 8 warps per CTA
#define W     8             // warps per CTA
#define K     4             // columns per thread  (C*TPB*K == Mm)
#define LOG2E 1.4426950408889634f

__device__ float g_rmin[Nn];

// ---------------------------------------------------------------------------
__global__ void softrr_init(const float* __restrict__ V) {
    const int b = blockIdx.x, t = threadIdx.x;
    const float* row = V + (size_t)b * Mm;
    float mn = FLT_MAX;
    for (int j = t; j < Mm; j += 256) mn = fminf(mn, row[j]);
    #pragma unroll
    for (int o = 16; o; o >>= 1) mn = fminf(mn, __shfl_down_sync(0xffffffffu, mn, o));
    __shared__ float s[8];
    if ((t & 31) == 0) s[t >> 5] = mn;
    __syncthreads();
    if (t == 0) {
        float r = s[0];
        #pragma unroll
        for (int w = 1; w < 8; w++) r = fminf(r, s[w]);
        g_rmin[b] = r;
    }
}

// ------------------------- primitives --------------------------------------
__device__ __forceinline__ void ld_vol_v4(uint32_t a, float4& f) {
    asm volatile("ld.volatile.shared.v4.f32 {%0,%1,%2,%3}, [%4];"
                 : "=f"(f.x), "=f"(f.y), "=f"(f.z), "=f"(f.w) : "r"(a));
}
__device__ __forceinline__ void st_vol_f32(uint32_t a, float v) {
    asm volatile("st.volatile.shared.f32 [%0], %1;" :: "r"(a), "f"(v) : "memory");
}
__device__ __forceinline__ uint32_t mapa_rank(uint32_t local_addr, int rank) {
    uint32_t ra;
    asm volatile("mapa.shared::cluster.u32 %0, %1, %2;" : "=r"(ra) : "r"(local_addr), "r"(rank));
    return ra;
}
__device__ __forceinline__ void st_cluster_f32(uint32_t ra, float v) {
    asm volatile("st.shared::cluster.f32 [%0], %1;" :: "r"(ra), "f"(v) : "memory");
}
// Remote arrive with release at cluster scope: orders the preceding data store.
__device__ __forceinline__ void mbar_arrive_remote(uint32_t ra) {
    asm volatile("mbarrier.arrive.release.cluster.shared::cluster.b64 _, [%0];"
                 :: "r"(ra) : "memory");
}
__device__ __forceinline__ float ex2(float z) {
    float e; asm("ex2.approx.f32 %0, %1;" : "=f"(e) : "f"(z));
    return e;
}
__device__ __forceinline__ float rcp(float x) {
    float r; asm("rcp.approx.f32 %0, %1;" : "=f"(r) : "f"(x));
    return r;
}

// ---------------------------------------------------------------------------
// ONE cluster: 8 CTAs x 256 threads x 4 cols/thread (R4 skeleton).
// NEW: cross-CTA sync via mbarrier sleep/wake instead of volatile polling.
// Per step r (phase ph=r&1, sign parity neg=(r>>1)&1 for the LOCAL relay ring):
//   all warps : e_k = 2^(a2_k*c_k); p = xor-butterfly(fixed tree of 4);
//               lane0 STS ±p -> s_wp[ph][wid]
//   warp 0    : sign-parity poll of the 2 s_wp quads (local, R4-proven),
//               P = fixed sum of 8 |.|; lane i<8: st.shared::cluster P into
//               peer i's slot[ph][rank], then mbarrier.arrive.release.cluster
//               on peer i's mbar (release orders the data store).
//   all thrds : mbarrier.try_wait.parity.acquire (HW sleep, wake ~60cyc after
//               the 8th arrive), then read 2 local slot quads (stable,
//               acquire-ordered), S = fixed pairwise sum of 8.
//   epilogue  : rinv=rcp(S); y=e*rinv; out[row]=o_acc+y; c=fma(-y,c,c).
// Slot ring depth 2: publisher of step r+2 passed wait(r+1), which required
// every CTA to have read slot[r] -> overwrite is safe. mbar count = C = 8
// arrivals per phase, parity = r&1.
// ---------------------------------------------------------------------------
__global__ void __launch_bounds__(TPB, 1) __cluster_dims__(C, 1, 1)
softrr_main(const float* __restrict__ V, float* __restrict__ out) {
    __shared__ float s_rmin[Nn];
    __shared__ __align__(16) float s_wp[2 * W];      // [phase][warp]
    __shared__ __align__(16) float s_slot[2 * C];    // [phase][rank]
    __shared__ __align__(8)  unsigned long long s_mbar;

    const int tid  = threadIdx.x;
    const int lane = tid & 31;
    const int wid  = tid >> 5;
    const int rank = blockIdx.x;
    const int col0 = rank * (TPB * K) + tid;          // cols: col0 + k*TPB

    const uint32_t wp_base   = (uint32_t)__cvta_generic_to_shared(s_wp);
    const uint32_t slot_base = (uint32_t)__cvta_generic_to_shared(s_slot);
    const uint32_t mbar_addr = (uint32_t)__cvta_generic_to_shared(&s_mbar);

    // hoisted remote addresses (warp0 lanes 0..C-1 -> peer `lane`)
    uint32_t r_slot = 0, r_mbar = 0;
    if (wid == 0 && lane < C) {
        r_slot = mapa_rank(slot_base, lane) + (uint32_t)rank * 4u;  // +ph*C*4
        r_mbar = mapa_rank(mbar_addr, lane);
    }

    if (tid < 2 * W) s_wp[tid]   = 0.0f;
    if (tid < 2 * C) s_slot[tid] = 0.0f;
    if (tid == 0)
        asm volatile("mbarrier.init.shared.b64 [%0], %1;" :: "r"(mbar_addr), "r"(C) : "memory");
    #pragma unroll
    for (int i = 0; i < Nn / TPB; i++) s_rmin[i * TPB + tid] = g_rmin[i * TPB + tid];
    __syncthreads();
    // all CTAs' mbarriers must be initialized before any remote arrive
    asm volatile("barrier.cluster.arrive.aligned;" ::: "memory");
    asm volatile("barrier.cluster.wait.aligned;"   ::: "memory");

    float c[K], a2[K], o_acc[K], a2n[K], o_nx[K];
    #pragma unroll
    for (int k = 0; k < K; k++) {
        c[k]     = 1.0f;
        a2[k]    = (V[col0 + k * TPB] - s_rmin[0] + 1.0f) * LOG2E;  // row 0
        o_acc[k] = 0.0f;                                            // round 0 overwrites
    }

    for (int r = 0; r < STEPS; r++) {
        const int  ph  = r & 1;
        const bool neg = (r >> 1) & 1;

        // --- produce: 4 exps, fixed tree, butterfly, STS relay
        float e[K];
        #pragma unroll
        for (int k = 0; k < K; k++) e[k] = ex2(a2[k] * c[k]);
        float p = (e[0] + e[1]) + (e[2] + e[3]);
        #pragma unroll
        for (int o = 16; o; o >>= 1) p += __shfl_xor_sync(0xffffffffu, p, o);
        if (lane == 0)
            st_vol_f32(wp_base + (uint32_t)(ph * W + wid) * 4u, neg ? -p : p);

        // --- warp0 relay: local sign-parity poll (R4-proven), then remote
        //     data store + release-arrive per peer
        if (wid == 0) {
            const uint32_t wa = wp_base + (uint32_t)(ph * W) * 4u;
            float4 Wa, Wb; bool ok;
            do {
                ld_vol_v4(wa,      Wa);
                ld_vol_v4(wa + 16, Wb);
                if (neg) ok = (Wa.x < 0.f) & (Wa.y < 0.f) & (Wa.z < 0.f) & (Wa.w < 0.f) &
                              (Wb.x < 0.f) & (Wb.y < 0.f) & (Wb.z < 0.f) & (Wb.w < 0.f);
                else     ok = (Wa.x > 0.f) & (Wa.y > 0.f) & (Wa.z > 0.f) & (Wa.w > 0.f) &
                              (Wb.x > 0.f) & (Wb.y > 0.f) & (Wb.z > 0.f) & (Wb.w > 0.f);
            } while (!ok);
            const float P = ((fabsf(Wa.x) + fabsf(Wa.y)) + (fabsf(Wa.z) + fabsf(Wa.w)))
                          + ((fabsf(Wb.x) + fabsf(Wb.y)) + (fabsf(Wb.z) + fabsf(Wb.w)));
            if (lane < C) {
                st_cluster_f32(r_slot + (uint32_t)(ph * C) * 4u, P);
                mbar_arrive_remote(r_mbar);
            }
        }

        // --- latency slack: prefetch next row's V / out (overlaps fabric flight)
        if (r + 1 < STEPS) {
            const int rn = (r + 1) & (Nn - 1);
            const float rm = s_rmin[rn];
            #pragma unroll
            for (int k = 0; k < K; k++) {
                a2n[k] = (V[(size_t)rn * Mm + col0 + k * TPB] - rm + 1.0f) * LOG2E;
                o_nx[k] = (r + 1 >= Nn) ? out[(size_t)rn * Mm + col0 + k * TPB] : 0.0f;
            }
        }

        // --- consume: HW sleep until all 8 arrives of this phase, then read
        {
            uint32_t done;
            do {
                asm volatile(
                    "{\n\t.reg .pred p;\n\t"
                    "mbarrier.try_wait.parity.acquire.cluster.shared::cta.b64 p, [%1], %2;\n\t"
                    "selp.b32 %0, 1, 0, p;\n\t}"
                    : "=r"(done) : "r"(mbar_addr), "r"((uint32_t)ph) : "memory");
            } while (!done);
        }
        float4 A, B;
        ld_vol_v4(slot_base + (uint32_t)(ph * C) * 4u,      A);
        ld_vol_v4(slot_base + (uint32_t)(ph * C) * 4u + 16, B);
        const float S = ((A.x + A.y) + (A.z + A.w)) + ((B.x + B.y) + (B.z + B.w));

        // --- epilogue
        const float rinv = rcp(S);
        const int   row  = r & (Nn - 1);
        #pragma unroll
        for (int k = 0; k < K; k++) {
            const float y = e[k] * rinv;
            out[(size_t)row * Mm + col0 + k * TPB] = o_acc[k] + y;
            c[k]     = __fmaf_rn(-y, c[k], c[k]);
            a2[k]    = a2n[k];
            o_acc[k] = o_nx[k];
        }
    }

    // hygiene: no CTA exits while peers might still target its smem
    asm volatile("barrier.cluster.arrive.aligned;" ::: "memory");
    asm volatile("barrier.cluster.wait.aligned;"   ::: "memory");
}

extern "C" void kernel_launch(void* const* d_in, const int* in_sizes, int n_in,
                              void* d_out, int out_size) {
    const float* V = (const float*)d_in[0];
    float* out = (float*)d_out;
    (void)in_sizes; (void)n_in; (void)out_size;

    softrr_init<<<Nn, 256>>>(V);
    softrr_main<<<C, TPB>>>(V, out);
}